// round 3
// baseline (speedup 1.0000x reference)
#include <cuda_runtime.h>
#include <cuda_bf16.h>
#include <cstdint>

#define NTHREADS 128
#define T_MASK 524287u           // T = 2^19
#define HPI2 2654435761u
#define HPI3 805459861u

__device__ __constant__ int c_NL[16] =
    {16, 22, 30, 42, 58, 80, 110, 152, 210, 290, 400, 552, 762, 1052, 1452, 2004};

// ---- packed f32x2 helpers (Blackwell fma.rn.f32x2) ----
typedef unsigned long long u64;

__device__ __forceinline__ u64 pack2(float lo, float hi) {
    u64 r; asm("mov.b64 %0, {%1, %2};" : "=l"(r) : "f"(lo), "f"(hi)); return r;
}
__device__ __forceinline__ void unpack2(u64 v, float& lo, float& hi) {
    asm("mov.b64 {%0, %1}, %2;" : "=f"(lo), "=f"(hi) : "l"(v));
}
__device__ __forceinline__ u64 fma2(u64 a, u64 b, u64 c) {
    u64 r; asm("fma.rn.f32x2 %0, %1, %2, %3;" : "=l"(r) : "l"(a), "l"(b), "l"(c)); return r;
}

__device__ __forceinline__ float reduce_2pi(float x) {
    float k = rintf(x * 0.15915494309189535f);          // x / (2*pi)
    return fmaf(k, -6.283185307179586f, x);
}

__global__ __launch_bounds__(NTHREADS) void ngp_fused_kernel(
    const float* __restrict__ x, const float* __restrict__ dirs,
    const float* __restrict__ tables,
    const float* __restrict__ w1, const float* __restrict__ b1,
    const float* __restrict__ w2, const float* __restrict__ b2,
    const float* __restrict__ w3, const float* __restrict__ b3,
    const float* __restrict__ w4, const float* __restrict__ b4,
    const float* __restrict__ w5, const float* __restrict__ b5,
    float* __restrict__ out, int N)
{
    __shared__ __align__(16) float s_w1[32 * 64];
    __shared__ __align__(16) float s_b1[64];
    __shared__ __align__(16) float s_w2[64 * 16];
    __shared__ __align__(16) float s_b2[16];
    __shared__ __align__(16) float s_w3[43 * 64];
    __shared__ __align__(16) float s_b3[64];
    __shared__ __align__(16) float s_w4t[64 * 64];   // transposed: [out][in]
    __shared__ __align__(16) float s_b4[64];
    __shared__ __align__(16) float s_w5[64 * 3];
    __shared__ __align__(16) float s_b5[3];

    for (int i = threadIdx.x; i < 32 * 64; i += NTHREADS) s_w1[i] = w1[i];
    for (int i = threadIdx.x; i < 64;      i += NTHREADS) s_b1[i] = b1[i];
    for (int i = threadIdx.x; i < 64 * 16; i += NTHREADS) s_w2[i] = w2[i];
    for (int i = threadIdx.x; i < 16;      i += NTHREADS) s_b2[i] = b2[i];
    for (int i = threadIdx.x; i < 43 * 64; i += NTHREADS) s_w3[i] = w3[i];
    for (int i = threadIdx.x; i < 64;      i += NTHREADS) s_b3[i] = b3[i];
    for (int i = threadIdx.x; i < 64 * 64; i += NTHREADS) {
        int r = i >> 6, c = i & 63;
        s_w4t[c * 64 + r] = w4[i];
    }
    for (int i = threadIdx.x; i < 64;      i += NTHREADS) s_b4[i] = b4[i];
    for (int i = threadIdx.x; i < 64 * 3;  i += NTHREADS) s_w5[i] = w5[i];
    for (int i = threadIdx.x; i < 3;       i += NTHREADS) s_b5[i] = b5[i];
    __syncthreads();

    const int n = blockIdx.x * NTHREADS + threadIdx.x;
    if (n >= N) return;

    // ---- position, AABB mask, [0,1) coords ----
    const float px = x[3 * n + 0], py = x[3 * n + 1], pz = x[3 * n + 2];
    const float xsx = px / 3.0f, xsy = py / 3.0f, xsz = pz / 3.0f;
    const bool mask = (fabsf(xsx) < 0.5f) && (fabsf(xsy) < 0.5f) && (fabsf(xsz) < 0.5f);
    const float hi = 1.0f - 1e-7f;
    const float x01x = fminf(fmaxf(xsx + 0.5f, 0.0f), hi);
    const float x01y = fminf(fmaxf(xsy + 0.5f, 0.0f), hi);
    const float x01z = fminf(fmaxf(xsz + 0.5f, 0.0f), hi);

    // ---- hash encode, streamed into packed density layer-1 accumulators ----
    u64 h1p[32];
    {
        const u64* b1p = (const u64*)s_b1;
        #pragma unroll
        for (int j = 0; j < 32; j++) h1p[j] = b1p[j];
    }

    for (int lvl = 0; lvl < 16; ++lvl) {
        const float res = (float)c_NL[lvl];
        const float fx = x01x * res, fy = x01y * res, fz = x01z * res;
        const float flx = floorf(fx), fly = floorf(fy), flz = floorf(fz);
        const float tx = fx - flx, ty = fy - fly, tz = fz - flz;
        const uint32_t X = (uint32_t)flx, Y = (uint32_t)fly, Z = (uint32_t)flz;
        const float wx[2] = {1.0f - tx, tx};
        const float wy[2] = {1.0f - ty, ty};
        const float wz[2] = {1.0f - tz, tz};

        const float2* tab = (const float2*)tables + (size_t)lvl * 524288u;

        // issue all 8 gathers first (MLP=8), then reduce
        float2 g[8];
        #pragma unroll
        for (int c = 0; c < 8; c++) {
            const uint32_t cx = c & 1u, cy = (c >> 1) & 1u, cz = (c >> 2) & 1u;
            const uint32_t h = (X + cx) ^ ((Y + cy) * HPI2) ^ ((Z + cz) * HPI3);
            g[c] = __ldg(&tab[h & T_MASK]);
        }

        float f0 = 0.0f, f1 = 0.0f;
        #pragma unroll
        for (int c = 0; c < 8; c++) {
            const uint32_t cx = c & 1u, cy = (c >> 1) & 1u, cz = (c >> 2) & 1u;
            const float w = wx[cx] * wy[cy] * wz[cz];
            f0 = fmaf(w, g[c].x, f0);
            f1 = fmaf(w, g[c].y, f1);
        }

        // packed rank-2 update of h1 with this level's two features
        const u64 f0p = pack2(f0, f0);
        const u64 f1p = pack2(f1, f1);
        const ulonglong2* r0 = (const ulonglong2*)&s_w1[(2 * lvl + 0) * 64];
        const ulonglong2* r1 = (const ulonglong2*)&s_w1[(2 * lvl + 1) * 64];
        #pragma unroll
        for (int q = 0; q < 16; q++) {
            const ulonglong2 a = r0[q], b = r1[q];
            h1p[2 * q + 0] = fma2(f0p, a.x, fma2(f1p, b.x, h1p[2 * q + 0]));
            h1p[2 * q + 1] = fma2(f0p, a.y, fma2(f1p, b.y, h1p[2 * q + 1]));
        }
    }

    // ReLU h1 (unpack in place to scalar array for the broadcast layer)
    float h1[64];
    #pragma unroll
    for (int j = 0; j < 32; j++) {
        float lo, hh; unpack2(h1p[j], lo, hh);
        h1[2 * j + 0] = fmaxf(lo, 0.0f);
        h1[2 * j + 1] = fmaxf(hh, 0.0f);
    }

    // ---- density layer 2 (linear, packed): h2[16] ----
    u64 h2p[8];
    {
        const u64* b2p = (const u64*)s_b2;
        #pragma unroll
        for (int j = 0; j < 8; j++) h2p[j] = b2p[j];
    }
    #pragma unroll
    for (int i = 0; i < 64; i++) {
        const u64 vp = pack2(h1[i], h1[i]);
        const ulonglong2* r = (const ulonglong2*)&s_w2[i * 16];
        #pragma unroll
        for (int q = 0; q < 4; q++) {
            const ulonglong2 a = r[q];
            h2p[2 * q + 0] = fma2(vp, a.x, h2p[2 * q + 0]);
            h2p[2 * q + 1] = fma2(vp, a.y, h2p[2 * q + 1]);
        }
    }
    float h2[16];
    #pragma unroll
    for (int j = 0; j < 8; j++) unpack2(h2p[j], h2[2 * j], h2[2 * j + 1]);

    const float log_sigma = mask ? h2[0] : -100000.0f;

    // ---- color layer 1 (packed): stream xi[43] into c1 accumulators ----
    u64 c1p[32];
    {
        const u64* b3p = (const u64*)s_b3;
        #pragma unroll
        for (int j = 0; j < 32; j++) c1p[j] = b3p[j];
    }

    const float dv[3] = {dirs[3 * n + 0], dirs[3 * n + 1], dirs[3 * n + 2]};

    auto accum_c1 = [&](float v, int row) {
        const u64 vp = pack2(v, v);
        const ulonglong2* r = (const ulonglong2*)&s_w3[row * 64];
        #pragma unroll
        for (int q = 0; q < 16; q++) {
            const ulonglong2 a = r[q];
            c1p[2 * q + 0] = fma2(vp, a.x, c1p[2 * q + 0]);
            c1p[2 * q + 1] = fma2(vp, a.y, c1p[2 * q + 1]);
        }
    };

    #pragma unroll
    for (int k = 0; k < 3; k++) accum_c1(dv[k], k);
    #pragma unroll
    for (int k = 0; k < 3; k++) {
        #pragma unroll
        for (int o = 0; o < 4; o++) {
            const float ang = reduce_2pi(dv[k] * (float)(1 << o));
            float sv, cv;
            sincosf(ang, &sv, &cv);
            accum_c1(sv, 3 + k * 4 + o);
            accum_c1(cv, 15 + k * 4 + o);
        }
    }
    #pragma unroll
    for (int j = 0; j < 16; j++) accum_c1(h2[j], 27 + j);

    // ReLU c1 in packed form
    #pragma unroll
    for (int j = 0; j < 32; j++) {
        float lo, hh; unpack2(c1p[j], lo, hh);
        c1p[j] = pack2(fmaxf(lo, 0.0f), fmaxf(hh, 0.0f));
    }

    // ---- color layer 2 + 3: packed dot against transposed w4, fold into 3 accums ----
    float col0 = s_b5[0], col1 = s_b5[1], col2 = s_b5[2];
    #pragma unroll
    for (int j = 0; j < 64; j++) {
        u64 acc2 = pack2(s_b4[j], 0.0f);
        const ulonglong2* r = (const ulonglong2*)&s_w4t[j * 64];
        #pragma unroll
        for (int q = 0; q < 16; q++) {
            const ulonglong2 a = r[q];
            acc2 = fma2(c1p[2 * q + 0], a.x, acc2);
            acc2 = fma2(c1p[2 * q + 1], a.y, acc2);
        }
        float alo, ahi; unpack2(acc2, alo, ahi);
        const float acc = fmaxf(alo + ahi, 0.0f);
        col0 = fmaf(acc, s_w5[j * 3 + 0], col0);
        col1 = fmaf(acc, s_w5[j * 3 + 1], col1);
        col2 = fmaf(acc, s_w5[j * 3 + 2], col2);
    }

    // sigmoid + mask
    col0 = 1.0f / (1.0f + __expf(-col0));
    col1 = 1.0f / (1.0f + __expf(-col1));
    col2 = 1.0f / (1.0f + __expf(-col2));
    if (!mask) { col0 = 0.0f; col1 = 0.0f; col2 = 0.0f; }

    out[3 * n + 0] = col0;
    out[3 * n + 1] = col1;
    out[3 * n + 2] = col2;
    out[3 * (size_t)N + n] = log_sigma;
}

extern "C" void kernel_launch(void* const* d_in, const int* in_sizes, int n_in,
                              void* d_out, int out_size) {
    const float* x      = (const float*)d_in[0];
    const float* dirs   = (const float*)d_in[1];
    const float* tables = (const float*)d_in[2];
    const float* w1 = (const float*)d_in[3];
    const float* b1 = (const float*)d_in[4];
    const float* w2 = (const float*)d_in[5];
    const float* b2 = (const float*)d_in[6];
    const float* w3 = (const float*)d_in[7];
    const float* b3 = (const float*)d_in[8];
    const float* w4 = (const float*)d_in[9];
    const float* b4 = (const float*)d_in[10];
    const float* w5 = (const float*)d_in[11];
    const float* b5 = (const float*)d_in[12];
    float* out = (float*)d_out;

    const int N = in_sizes[0] / 3;
    const int blocks = (N + NTHREADS - 1) / NTHREADS;
    ngp_fused_kernel<<<blocks, NTHREADS>>>(x, dirs, tables,
                                           w1, b1, w2, b2, w3, b3, w4, b4, w5, b5,
                                           out, N);
}

// round 4
// speedup vs baseline: 1.0059x; 1.0059x over previous
#include <cuda_runtime.h>
#include <cuda_bf16.h>
#include <cstdint>

#define NTHREADS 128
#define T_MASK 524287u           // T = 2^19
#define HPI2 2654435761u
#define HPI3 805459861u

__device__ __constant__ int c_NL[16] =
    {16, 22, 30, 42, 58, 80, 110, 152, 210, 290, 400, 552, 762, 1052, 1452, 2004};

// ---- packed f32x2 helpers (Blackwell fma.rn.f32x2) ----
typedef unsigned long long u64;

__device__ __forceinline__ u64 pack2(float lo, float hi) {
    u64 r; asm("mov.b64 %0, {%1, %2};" : "=l"(r) : "f"(lo), "f"(hi)); return r;
}
__device__ __forceinline__ void unpack2(u64 v, float& lo, float& hi) {
    asm("mov.b64 {%0, %1}, %2;" : "=f"(lo), "=f"(hi) : "l"(v));
}
__device__ __forceinline__ u64 fma2(u64 a, u64 b, u64 c) {
    u64 r; asm("fma.rn.f32x2 %0, %1, %2, %3;" : "=l"(r) : "l"(a), "l"(b), "l"(c)); return r;
}

__device__ __forceinline__ float reduce_2pi(float x) {
    float k = rintf(x * 0.15915494309189535f);          // x / (2*pi)
    return fmaf(k, -6.283185307179586f, x);
}

__global__ __launch_bounds__(NTHREADS, 2) void ngp_fused_kernel(
    const float* __restrict__ x, const float* __restrict__ dirs,
    const float* __restrict__ tables,
    const float* __restrict__ w1, const float* __restrict__ b1,
    const float* __restrict__ w2, const float* __restrict__ b2,
    const float* __restrict__ w3, const float* __restrict__ b3,
    const float* __restrict__ w4, const float* __restrict__ b4,
    const float* __restrict__ w5, const float* __restrict__ b5,
    float* __restrict__ out, int N)
{
    __shared__ __align__(16) float s_w1[32 * 64];
    __shared__ __align__(16) float s_b1[64];
    __shared__ __align__(16) float s_w2[64 * 16];
    __shared__ __align__(16) float s_b2[16];
    __shared__ __align__(16) float s_w3[43 * 64];
    __shared__ __align__(16) float s_b3[64];
    __shared__ __align__(16) float s_w4t[64 * 64];   // transposed: [out][in]
    __shared__ __align__(16) float s_b4[64];
    __shared__ __align__(16) float s_w5[64 * 3];
    __shared__ __align__(16) float s_b5[3];

    for (int i = threadIdx.x; i < 32 * 64; i += NTHREADS) s_w1[i] = w1[i];
    for (int i = threadIdx.x; i < 64;      i += NTHREADS) s_b1[i] = b1[i];
    for (int i = threadIdx.x; i < 64 * 16; i += NTHREADS) s_w2[i] = w2[i];
    for (int i = threadIdx.x; i < 16;      i += NTHREADS) s_b2[i] = b2[i];
    for (int i = threadIdx.x; i < 43 * 64; i += NTHREADS) s_w3[i] = w3[i];
    for (int i = threadIdx.x; i < 64;      i += NTHREADS) s_b3[i] = b3[i];
    for (int i = threadIdx.x; i < 64 * 64; i += NTHREADS) {
        int r = i >> 6, c = i & 63;
        s_w4t[c * 64 + r] = w4[i];
    }
    for (int i = threadIdx.x; i < 64;      i += NTHREADS) s_b4[i] = b4[i];
    for (int i = threadIdx.x; i < 64 * 3;  i += NTHREADS) s_w5[i] = w5[i];
    for (int i = threadIdx.x; i < 3;       i += NTHREADS) s_b5[i] = b5[i];
    __syncthreads();

    // two points per thread: nA and nB = nA + NTHREADS
    const int nA = blockIdx.x * (2 * NTHREADS) + threadIdx.x;
    const int nB = nA + NTHREADS;
    if (nA >= N) return;
    const bool hasB = (nB < N);
    const int nBs = hasB ? nB : nA;   // safe index for loads

    // ---- position, AABB mask, [0,1) coords (both points) ----
    float x01[2][3];
    bool msk[2];
    {
        const int nn[2] = {nA, nBs};
        #pragma unroll
        for (int p = 0; p < 2; p++) {
            const float sx = x[3 * nn[p] + 0] * (1.0f / 3.0f);
            const float sy = x[3 * nn[p] + 1] * (1.0f / 3.0f);
            const float sz = x[3 * nn[p] + 2] * (1.0f / 3.0f);
            msk[p] = (fabsf(sx) < 0.5f) && (fabsf(sy) < 0.5f) && (fabsf(sz) < 0.5f);
            const float hi = 1.0f - 1e-7f;
            x01[p][0] = fminf(fmaxf(sx + 0.5f, 0.0f), hi);
            x01[p][1] = fminf(fmaxf(sy + 0.5f, 0.0f), hi);
            x01[p][2] = fminf(fmaxf(sz + 0.5f, 0.0f), hi);
        }
    }

    // ---- hash encode -> packed density layer-1 accumulators (both points) ----
    u64 h1pA[32], h1pB[32];
    {
        const u64* b1p = (const u64*)s_b1;
        #pragma unroll
        for (int j = 0; j < 32; j++) { h1pA[j] = b1p[j]; h1pB[j] = b1p[j]; }
    }

    for (int lvl = 0; lvl < 16; ++lvl) {
        const float res = (float)c_NL[lvl];
        const float2* tab = (const float2*)tables + (size_t)lvl * 524288u;

        float f0v[2], f1v[2];
        #pragma unroll
        for (int p = 0; p < 2; p++) {
            const float fx = x01[p][0] * res, fy = x01[p][1] * res, fz = x01[p][2] * res;
            const float flx = floorf(fx), fly = floorf(fy), flz = floorf(fz);
            const float tx = fx - flx, ty = fy - fly, tz = fz - flz;
            const uint32_t X = (uint32_t)flx, Y = (uint32_t)fly, Z = (uint32_t)flz;
            const float wx[2] = {1.0f - tx, tx};
            const float wy[2] = {1.0f - ty, ty};
            const float wz[2] = {1.0f - tz, tz};

            float2 g[8];
            #pragma unroll
            for (int c = 0; c < 8; c++) {
                const uint32_t cx = c & 1u, cy = (c >> 1) & 1u, cz = (c >> 2) & 1u;
                const uint32_t h = (X + cx) ^ ((Y + cy) * HPI2) ^ ((Z + cz) * HPI3);
                g[c] = __ldg(&tab[h & T_MASK]);
            }
            float f0 = 0.0f, f1 = 0.0f;
            #pragma unroll
            for (int c = 0; c < 8; c++) {
                const uint32_t cx = c & 1u, cy = (c >> 1) & 1u, cz = (c >> 2) & 1u;
                const float w = wx[cx] * wy[cy] * wz[cz];
                f0 = fmaf(w, g[c].x, f0);
                f1 = fmaf(w, g[c].y, f1);
            }
            f0v[p] = f0; f1v[p] = f1;
        }

        // packed rank-2 update, weights loaded ONCE for both points
        const u64 f0A = pack2(f0v[0], f0v[0]), f1A = pack2(f1v[0], f1v[0]);
        const u64 f0B = pack2(f0v[1], f0v[1]), f1B = pack2(f1v[1], f1v[1]);
        const ulonglong2* r0 = (const ulonglong2*)&s_w1[(2 * lvl + 0) * 64];
        const ulonglong2* r1 = (const ulonglong2*)&s_w1[(2 * lvl + 1) * 64];
        #pragma unroll
        for (int q = 0; q < 16; q++) {
            const ulonglong2 a = r0[q], b = r1[q];
            h1pA[2 * q + 0] = fma2(f0A, a.x, fma2(f1A, b.x, h1pA[2 * q + 0]));
            h1pA[2 * q + 1] = fma2(f0A, a.y, fma2(f1A, b.y, h1pA[2 * q + 1]));
            h1pB[2 * q + 0] = fma2(f0B, a.x, fma2(f1B, b.x, h1pB[2 * q + 0]));
            h1pB[2 * q + 1] = fma2(f0B, a.y, fma2(f1B, b.y, h1pB[2 * q + 1]));
        }
    }

    // ReLU h1 -> scalar arrays
    float h1A[64], h1B[64];
    #pragma unroll
    for (int j = 0; j < 32; j++) {
        float lo, hh;
        unpack2(h1pA[j], lo, hh);
        h1A[2 * j] = fmaxf(lo, 0.0f); h1A[2 * j + 1] = fmaxf(hh, 0.0f);
        unpack2(h1pB[j], lo, hh);
        h1B[2 * j] = fmaxf(lo, 0.0f); h1B[2 * j + 1] = fmaxf(hh, 0.0f);
    }

    // ---- density layer 2 (linear, packed, shared weight reads) ----
    u64 h2pA[8], h2pB[8];
    {
        const u64* b2p = (const u64*)s_b2;
        #pragma unroll
        for (int j = 0; j < 8; j++) { h2pA[j] = b2p[j]; h2pB[j] = b2p[j]; }
    }
    #pragma unroll
    for (int i = 0; i < 64; i++) {
        const u64 vA = pack2(h1A[i], h1A[i]);
        const u64 vB = pack2(h1B[i], h1B[i]);
        const ulonglong2* r = (const ulonglong2*)&s_w2[i * 16];
        #pragma unroll
        for (int q = 0; q < 4; q++) {
            const ulonglong2 a = r[q];
            h2pA[2 * q + 0] = fma2(vA, a.x, h2pA[2 * q + 0]);
            h2pA[2 * q + 1] = fma2(vA, a.y, h2pA[2 * q + 1]);
            h2pB[2 * q + 0] = fma2(vB, a.x, h2pB[2 * q + 0]);
            h2pB[2 * q + 1] = fma2(vB, a.y, h2pB[2 * q + 1]);
        }
    }
    float h2A[16], h2B[16];
    #pragma unroll
    for (int j = 0; j < 8; j++) {
        unpack2(h2pA[j], h2A[2 * j], h2A[2 * j + 1]);
        unpack2(h2pB[j], h2B[2 * j], h2B[2 * j + 1]);
    }

    const float logSigA = msk[0] ? h2A[0] : -100000.0f;
    const float logSigB = msk[1] ? h2B[0] : -100000.0f;

    // ---- color layer 1 (packed, shared weight reads) ----
    u64 c1pA[32], c1pB[32];
    {
        const u64* b3p = (const u64*)s_b3;
        #pragma unroll
        for (int j = 0; j < 32; j++) { c1pA[j] = b3p[j]; c1pB[j] = b3p[j]; }
    }

    float dvA[3], dvB[3];
    #pragma unroll
    for (int k = 0; k < 3; k++) { dvA[k] = dirs[3 * nA + k]; dvB[k] = dirs[3 * nBs + k]; }

    auto accum2 = [&](float vA, float vB, int row) {
        const u64 pA = pack2(vA, vA);
        const u64 pB = pack2(vB, vB);
        const ulonglong2* r = (const ulonglong2*)&s_w3[row * 64];
        #pragma unroll
        for (int q = 0; q < 16; q++) {
            const ulonglong2 a = r[q];
            c1pA[2 * q + 0] = fma2(pA, a.x, c1pA[2 * q + 0]);
            c1pA[2 * q + 1] = fma2(pA, a.y, c1pA[2 * q + 1]);
            c1pB[2 * q + 0] = fma2(pB, a.x, c1pB[2 * q + 0]);
            c1pB[2 * q + 1] = fma2(pB, a.y, c1pB[2 * q + 1]);
        }
    };

    #pragma unroll
    for (int k = 0; k < 3; k++) accum2(dvA[k], dvB[k], k);
    #pragma unroll
    for (int k = 0; k < 3; k++) {
        #pragma unroll
        for (int o = 0; o < 4; o++) {
            const float aA = reduce_2pi(dvA[k] * (float)(1 << o));
            const float aB = reduce_2pi(dvB[k] * (float)(1 << o));
            float sA, cA, sB, cB;
            sincosf(aA, &sA, &cA);
            sincosf(aB, &sB, &cB);
            accum2(sA, sB, 3 + k * 4 + o);
            accum2(cA, cB, 15 + k * 4 + o);
        }
    }
    #pragma unroll
    for (int j = 0; j < 16; j++) accum2(h2A[j], h2B[j], 27 + j);

    // ReLU c1 in packed form
    #pragma unroll
    for (int j = 0; j < 32; j++) {
        float lo, hh;
        unpack2(c1pA[j], lo, hh);
        c1pA[j] = pack2(fmaxf(lo, 0.0f), fmaxf(hh, 0.0f));
        unpack2(c1pB[j], lo, hh);
        c1pB[j] = pack2(fmaxf(lo, 0.0f), fmaxf(hh, 0.0f));
    }

    // ---- color layer 2 + 3 (shared weight reads) ----
    float colA0 = s_b5[0], colA1 = s_b5[1], colA2 = s_b5[2];
    float colB0 = s_b5[0], colB1 = s_b5[1], colB2 = s_b5[2];
    #pragma unroll
    for (int j = 0; j < 64; j++) {
        const float bj = s_b4[j];
        u64 accA = pack2(bj, 0.0f);
        u64 accB = pack2(bj, 0.0f);
        const ulonglong2* r = (const ulonglong2*)&s_w4t[j * 64];
        #pragma unroll
        for (int q = 0; q < 16; q++) {
            const ulonglong2 a = r[q];
            accA = fma2(c1pA[2 * q + 0], a.x, accA);
            accA = fma2(c1pA[2 * q + 1], a.y, accA);
            accB = fma2(c1pB[2 * q + 0], a.x, accB);
            accB = fma2(c1pB[2 * q + 1], a.y, accB);
        }
        float lo, hh;
        unpack2(accA, lo, hh);
        const float aA = fmaxf(lo + hh, 0.0f);
        unpack2(accB, lo, hh);
        const float aB = fmaxf(lo + hh, 0.0f);
        const float w50 = s_w5[j * 3 + 0], w51 = s_w5[j * 3 + 1], w52 = s_w5[j * 3 + 2];
        colA0 = fmaf(aA, w50, colA0); colA1 = fmaf(aA, w51, colA1); colA2 = fmaf(aA, w52, colA2);
        colB0 = fmaf(aB, w50, colB0); colB1 = fmaf(aB, w51, colB1); colB2 = fmaf(aB, w52, colB2);
    }

    // sigmoid + mask + store
    colA0 = 1.0f / (1.0f + __expf(-colA0));
    colA1 = 1.0f / (1.0f + __expf(-colA1));
    colA2 = 1.0f / (1.0f + __expf(-colA2));
    if (!msk[0]) { colA0 = 0.0f; colA1 = 0.0f; colA2 = 0.0f; }
    out[3 * nA + 0] = colA0;
    out[3 * nA + 1] = colA1;
    out[3 * nA + 2] = colA2;
    out[3 * (size_t)N + nA] = logSigA;

    if (hasB) {
        colB0 = 1.0f / (1.0f + __expf(-colB0));
        colB1 = 1.0f / (1.0f + __expf(-colB1));
        colB2 = 1.0f / (1.0f + __expf(-colB2));
        if (!msk[1]) { colB0 = 0.0f; colB1 = 0.0f; colB2 = 0.0f; }
        out[3 * nB + 0] = colB0;
        out[3 * nB + 1] = colB1;
        out[3 * nB + 2] = colB2;
        out[3 * (size_t)N + nB] = logSigB;
    }
}

extern "C" void kernel_launch(void* const* d_in, const int* in_sizes, int n_in,
                              void* d_out, int out_size) {
    const float* x      = (const float*)d_in[0];
    const float* dirs   = (const float*)d_in[1];
    const float* tables = (const float*)d_in[2];
    const float* w1 = (const float*)d_in[3];
    const float* b1 = (const float*)d_in[4];
    const float* w2 = (const float*)d_in[5];
    const float* b2 = (const float*)d_in[6];
    const float* w3 = (const float*)d_in[7];
    const float* b3 = (const float*)d_in[8];
    const float* w4 = (const float*)d_in[9];
    const float* b4 = (const float*)d_in[10];
    const float* w5 = (const float*)d_in[11];
    const float* b5 = (const float*)d_in[12];
    float* out = (float*)d_out;

    const int N = in_sizes[0] / 3;
    const int blocks = (N + 2 * NTHREADS - 1) / (2 * NTHREADS);
    ngp_fused_kernel<<<blocks, NTHREADS>>>(x, dirs, tables,
                                           w1, b1, w2, b2, w3, b3, w4, b4, w5, b5,
                                           out, N);
}